// round 15
// baseline (speedup 1.0000x reference)
#include <cuda_runtime.h>
#include <cuda_bf16.h>
#include <math.h>

// 3-layer GCN, N=50000, E=800000, dims 128->64->64->32.
// Layer: out[d] = dis[d]*( sum_{s->d} dis[s]*h[s] + dis[d]*h[d] ) + b, h = in@W
// CSR-by-dst gather; CSR build on forked stream concurrent with gemm1.
// Boundary GEMMs fused into the gathers WARP-LOCALLY (shfl within 16-lane node
// segments, no block barrier): gather1+gemm2 -> hs2, gather2+gemm3 -> hs3.

#define NMAX 50000
#define EMAX 800000

__device__ float g_hs1[NMAX * 64];   // gemm1 out (unscaled)
__device__ float g_hs2[NMAX * 64];   // fused1 out (pre-scaled h2)
__device__ float g_hs3[NMAX * 32];   // fused2 out (pre-scaled h3)
__device__ float g_dis[NMAX];
__device__ int   g_deg[NMAX];
__device__ int   g_scan[NMAX];
__device__ int   g_bsum[64];
__device__ int   g_rowptr[NMAX + 1];
__device__ int   g_cursor[NMAX];
__device__ int   g_col[EMAX];

// ---------------------------------------------------------------------------
// packed f32x2 helpers (sm_103a)
// ---------------------------------------------------------------------------
__device__ __forceinline__ unsigned long long pack2(float a, float b) {
    unsigned long long r;
    asm("mov.b64 %0, {%1, %2};" : "=l"(r) : "f"(a), "f"(b));
    return r;
}
__device__ __forceinline__ unsigned long long ffma2(unsigned long long a,
                                                    unsigned long long b,
                                                    unsigned long long c) {
    unsigned long long d;
    asm("fma.rn.f32x2 %0, %1, %2, %3;" : "=l"(d) : "l"(a), "l"(b), "l"(c));
    return d;
}
__device__ __forceinline__ unsigned long long fmul2(unsigned long long a,
                                                    unsigned long long b) {
    unsigned long long d;
    asm("mul.rn.f32x2 %0, %1, %2;" : "=l"(d) : "l"(a), "l"(b));
    return d;
}

// ---------------------------------------------------------------------------
// CSR build
// ---------------------------------------------------------------------------
__global__ void deg_count_kernel(const int* __restrict__ dst, int* deg, int e) {
    int q = blockIdx.x * blockDim.x + threadIdx.x;
    int base = q * 4;
    if (base + 4 <= e) {
        int4 d4 = *reinterpret_cast<const int4*>(dst + base);
        atomicAdd(&deg[d4.x], 1);
        atomicAdd(&deg[d4.y], 1);
        atomicAdd(&deg[d4.z], 1);
        atomicAdd(&deg[d4.w], 1);
    } else {
        for (int i = base; i < e; i++) atomicAdd(&deg[dst[i]], 1);
    }
}

__global__ void scan1_kernel(const int* __restrict__ deg, int* scanout,
                             int* bsum, int n) {
    __shared__ int s[1024];
    int i = blockIdx.x * 1024 + threadIdx.x;
    int v = (i < n) ? deg[i] : 0;
    s[threadIdx.x] = v;
    __syncthreads();
#pragma unroll
    for (int off = 1; off < 1024; off <<= 1) {
        int add = (threadIdx.x >= off) ? s[threadIdx.x - off] : 0;
        __syncthreads();
        s[threadIdx.x] += add;
        __syncthreads();
    }
    if (i < n) scanout[i] = s[threadIdx.x];
    if (threadIdx.x == 1023) bsum[blockIdx.x] = s[1023];
}

// Fixup with inlined bsum-prefix (each 256-thread block lies in one 1024-tile).
__global__ void fixup_kernel(const int* __restrict__ scanin,
                             const int* __restrict__ deg,
                             const int* __restrict__ bsum,
                             int* rowptr, int* cursor, float* dis,
                             int n, int e) {
    __shared__ int wsum[8];
    int tile = blockIdx.x >> 2;
    int part = 0;
    for (int j = threadIdx.x; j < tile; j += blockDim.x) part += bsum[j];
#pragma unroll
    for (int off = 16; off > 0; off >>= 1)
        part += __shfl_down_sync(0xFFFFFFFFu, part, off);
    if ((threadIdx.x & 31) == 0) wsum[threadIdx.x >> 5] = part;
    __syncthreads();
    if (threadIdx.x == 0) {
        int b = 0;
#pragma unroll
        for (int w = 0; w < 8; w++) b += wsum[w];
        wsum[0] = b;
    }
    __syncthreads();
    int base = wsum[0];

    int i = blockIdx.x * blockDim.x + threadIdx.x;
    if (i < n) {
        int d = deg[i];
        int rp = scanin[i] - d + base;
        rowptr[i] = rp;
        cursor[i] = rp;
        dis[i] = rsqrtf((float)(d + 1));  // +1 self loop
    }
    if (i == 0) rowptr[n] = e;
}

__global__ void fill_kernel(const int* __restrict__ src,
                            const int* __restrict__ dst,
                            int* cursor, int* col, int e) {
    int q = blockIdx.x * blockDim.x + threadIdx.x;
    int base = q * 4;
    if (base + 4 <= e) {
        int4 s4 = *reinterpret_cast<const int4*>(src + base);
        int4 d4 = *reinterpret_cast<const int4*>(dst + base);
        int p0 = atomicAdd(&cursor[d4.x], 1);
        int p1 = atomicAdd(&cursor[d4.y], 1);
        int p2 = atomicAdd(&cursor[d4.z], 1);
        int p3 = atomicAdd(&cursor[d4.w], 1);
        col[p0] = s4.x;
        col[p1] = s4.y;
        col[p2] = s4.z;
        col[p3] = s4.w;
    } else {
        for (int i = base; i < e; i++) {
            int p = atomicAdd(&cursor[dst[i]], 1);
            col[p] = src[i];
        }
    }
}

// ---------------------------------------------------------------------------
// GEMM1: hs[row,:] = in[row,:] @ W (no dis needed -> overlaps CSR build)
// ---------------------------------------------------------------------------
template <int IN, int OUT>
__global__ void gemm_kernel(const float* __restrict__ in,
                            const float* __restrict__ W,
                            float* __restrict__ hs, int n) {
    __shared__ __align__(16) float sW[IN * OUT];
    for (int i = threadIdx.x; i < IN * OUT / 4; i += blockDim.x)
        reinterpret_cast<float4*>(sW)[i] = reinterpret_cast<const float4*>(W)[i];
    __syncthreads();

    int row = blockIdx.x * blockDim.x + threadIdx.x;
    if (row >= n) return;

    unsigned long long acc[OUT / 2];
#pragma unroll
    for (int c = 0; c < OUT / 2; c++) acc[c] = 0ULL;

    const float* xr = in + (size_t)row * IN;
    for (int k0 = 0; k0 < IN; k0 += 4) {
        float4 xv = *reinterpret_cast<const float4*>(xr + k0);
        float xs[4] = {xv.x, xv.y, xv.z, xv.w};
#pragma unroll
        for (int kk = 0; kk < 4; kk++) {
            unsigned long long xx = pack2(xs[kk], xs[kk]);
            const ulonglong2* wr =
                reinterpret_cast<const ulonglong2*>(sW + (k0 + kk) * OUT);
#pragma unroll
            for (int c4 = 0; c4 < OUT / 4; c4++) {
                ulonglong2 w = wr[c4];
                acc[c4 * 2 + 0] = ffma2(xx, w.x, acc[c4 * 2 + 0]);
                acc[c4 * 2 + 1] = ffma2(xx, w.y, acc[c4 * 2 + 1]);
            }
        }
    }

    ulonglong2* hp = reinterpret_cast<ulonglong2*>(hs + (size_t)row * OUT);
#pragma unroll
    for (int c4 = 0; c4 < OUT / 4; c4++) {
        ulonglong2 r;
        r.x = acc[c4 * 2 + 0];
        r.y = acc[c4 * 2 + 1];
        hp[c4] = r;
    }
}

// ---------------------------------------------------------------------------
// Fused gather + warp-local GEMM boundary kernel (DIN=64 fixed).
//   Phase 1 (per node, 16 lanes): a = relu( dis[d]*(sum dis?[s]*hs[s] + self) + b )
//     -> activation float4 per lane, in registers.
//   Phase 2 (warp-local, shfl width 16): hs_out[node,:] = (a @ W) * dis[node]
// No block barrier; a warp's two nodes proceed independently of other warps.
// ---------------------------------------------------------------------------
template <int DOUT, bool DIS_SRC>
__global__ void gather_gemm_kernel(const int* __restrict__ rowptr,
                                   const int* __restrict__ col,
                                   const float* __restrict__ hs,
                                   const float* __restrict__ dis,
                                   const float* __restrict__ bias,
                                   const float* __restrict__ W,   // [64][DOUT]
                                   float* __restrict__ hs_out, int n) {
    const int DIN = 64;
    const int G = 16;  // lanes per node

    __shared__ __align__(16) float sW[DIN * DOUT];
    for (int i = threadIdx.x; i < DIN * DOUT / 4; i += blockDim.x)
        reinterpret_cast<float4*>(sW)[i] = reinterpret_cast<const float4*>(W)[i];
    __syncthreads();  // only for sW readiness (once, before any node work)

    int t = blockIdx.x * blockDim.x + threadIdx.x;
    int gid = t / G;
    int lane = t % G;
    if (gid >= n) return;  // whole 16-lane segment exits together

    unsigned seg_mask = 0xFFFFu << ((threadIdx.x & 16));  // lanes 0-15 or 16-31

    const float4* hs4 = reinterpret_cast<const float4*>(hs);
    int beg = rowptr[gid];
    int end = rowptr[gid + 1];
    float dself = dis[gid];

    // ---- phase 1: gather ----
    float4 a0 = hs4[(size_t)gid * G + lane];  // self term
    if (DIS_SRC) {
        a0.x *= dself; a0.y *= dself; a0.z *= dself; a0.w *= dself;
    }
#pragma unroll 4
    for (int e = beg; e < end; e++) {
        int s = __ldg(&col[e]);
        float4 v = hs4[(size_t)s * G + lane];
        if (DIS_SRC) {
            float ds = __ldg(&dis[s]);
            a0.x += v.x * ds; a0.y += v.y * ds;
            a0.z += v.z * ds; a0.w += v.w * ds;
        } else {
            a0.x += v.x; a0.y += v.y; a0.z += v.z; a0.w += v.w;
        }
    }
    float4 b4 = reinterpret_cast<const float4*>(bias)[lane];
    float4 r;  // activation: lane holds h[4*lane .. 4*lane+3]
    r.x = fmaxf(a0.x * dself + b4.x, 0.0f);
    r.y = fmaxf(a0.y * dself + b4.y, 0.0f);
    r.z = fmaxf(a0.z * dself + b4.z, 0.0f);
    r.w = fmaxf(a0.w * dself + b4.w, 0.0f);

    // ---- phase 2: warp-local GEMM via shfl broadcast (width 16) ----
    if (DOUT == 64) {
        int c0 = lane * 4;
        unsigned long long acc0 = 0ULL, acc1 = 0ULL;
#pragma unroll
        for (int j = 0; j < 16; j++) {
            float h0 = __shfl_sync(seg_mask, r.x, j, 16);
            float h1 = __shfl_sync(seg_mask, r.y, j, 16);
            float h2 = __shfl_sync(seg_mask, r.z, j, 16);
            float h3 = __shfl_sync(seg_mask, r.w, j, 16);
            const float* w0 = sW + (j * 4 + 0) * DOUT + c0;
            const float* w1 = sW + (j * 4 + 1) * DOUT + c0;
            const float* w2 = sW + (j * 4 + 2) * DOUT + c0;
            const float* w3 = sW + (j * 4 + 3) * DOUT + c0;
            ulonglong2 wv;
            wv = *reinterpret_cast<const ulonglong2*>(w0);
            acc0 = ffma2(pack2(h0, h0), wv.x, acc0);
            acc1 = ffma2(pack2(h0, h0), wv.y, acc1);
            wv = *reinterpret_cast<const ulonglong2*>(w1);
            acc0 = ffma2(pack2(h1, h1), wv.x, acc0);
            acc1 = ffma2(pack2(h1, h1), wv.y, acc1);
            wv = *reinterpret_cast<const ulonglong2*>(w2);
            acc0 = ffma2(pack2(h2, h2), wv.x, acc0);
            acc1 = ffma2(pack2(h2, h2), wv.y, acc1);
            wv = *reinterpret_cast<const ulonglong2*>(w3);
            acc0 = ffma2(pack2(h3, h3), wv.x, acc0);
            acc1 = ffma2(pack2(h3, h3), wv.y, acc1);
        }
        unsigned long long dd = pack2(dself, dself);
        ulonglong2 o;
        o.x = fmul2(acc0, dd);
        o.y = fmul2(acc1, dd);
        *reinterpret_cast<ulonglong2*>(hs_out + (size_t)gid * 64 + c0) = o;
    } else {  // DOUT == 32
        int c0 = lane * 2;
        unsigned long long acc0 = 0ULL;
#pragma unroll
        for (int j = 0; j < 16; j++) {
            float h0 = __shfl_sync(seg_mask, r.x, j, 16);
            float h1 = __shfl_sync(seg_mask, r.y, j, 16);
            float h2 = __shfl_sync(seg_mask, r.z, j, 16);
            float h3 = __shfl_sync(seg_mask, r.w, j, 16);
            acc0 = ffma2(pack2(h0, h0),
                *reinterpret_cast<const unsigned long long*>(sW + (j*4+0)*DOUT + c0), acc0);
            acc0 = ffma2(pack2(h1, h1),
                *reinterpret_cast<const unsigned long long*>(sW + (j*4+1)*DOUT + c0), acc0);
            acc0 = ffma2(pack2(h2, h2),
                *reinterpret_cast<const unsigned long long*>(sW + (j*4+2)*DOUT + c0), acc0);
            acc0 = ffma2(pack2(h3, h3),
                *reinterpret_cast<const unsigned long long*>(sW + (j*4+3)*DOUT + c0), acc0);
        }
        unsigned long long dd = pack2(dself, dself);
        *reinterpret_cast<unsigned long long*>(hs_out + (size_t)gid * 32 + c0) =
            fmul2(acc0, dd);
    }
}

// ---------------------------------------------------------------------------
// Final gather (layer 3, 32-wide fp32): out[d,:] = dis[d]*acc + b, no relu.
// ---------------------------------------------------------------------------
__global__ void gather_f32_kernel(const int* __restrict__ rowptr,
                                  const int* __restrict__ col,
                                  const float* __restrict__ hs,
                                  const float* __restrict__ dis,
                                  const float* __restrict__ bias,
                                  float* __restrict__ out, int n) {
    const int G = 8;
    int t = blockIdx.x * blockDim.x + threadIdx.x;
    int gid = t / G;
    int lane = t % G;
    if (gid >= n) return;

    const float4* hs4 = reinterpret_cast<const float4*>(hs);
    int beg = rowptr[gid];
    int end = rowptr[gid + 1];

    float dself = dis[gid];
    float4 a0 = hs4[(size_t)gid * G + lane];  // self term

#pragma unroll 4
    for (int e = beg; e < end; e++) {
        int s = __ldg(&col[e]);
        float4 v = hs4[(size_t)s * G + lane];
        a0.x += v.x; a0.y += v.y; a0.z += v.z; a0.w += v.w;
    }

    float4 b4 = reinterpret_cast<const float4*>(bias)[lane];
    float4 r;
    r.x = a0.x * dself + b4.x;
    r.y = a0.y * dself + b4.y;
    r.z = a0.z * dself + b4.z;
    r.w = a0.w * dself + b4.w;
    reinterpret_cast<float4*>(out)[(size_t)gid * G + lane] = r;
}

// ---------------------------------------------------------------------------
// launch
// ---------------------------------------------------------------------------
extern "C" void kernel_launch(void* const* d_in, const int* in_sizes, int n_in,
                              void* d_out, int out_size) {
    const float* x    = (const float*)d_in[0];
    const int*   eidx = (const int*)  d_in[1];
    const float* W1   = (const float*)d_in[2];
    const float* b1   = (const float*)d_in[3];
    const float* W2   = (const float*)d_in[4];
    const float* b2   = (const float*)d_in[5];
    const float* W3   = (const float*)d_in[6];
    const float* b3   = (const float*)d_in[7];

    const int N = in_sizes[0] / 128;
    const int E = in_sizes[1] / 2;
    const int* esrc = eidx;
    const int* edst = eidx + E;

    float *hs1, *hs2, *hs3, *dis;
    int *deg, *scn, *bsum, *rowptr, *cursor, *col;
    cudaGetSymbolAddress((void**)&hs1,    g_hs1);
    cudaGetSymbolAddress((void**)&hs2,    g_hs2);
    cudaGetSymbolAddress((void**)&hs3,    g_hs3);
    cudaGetSymbolAddress((void**)&dis,    g_dis);
    cudaGetSymbolAddress((void**)&deg,    g_deg);
    cudaGetSymbolAddress((void**)&scn,    g_scan);
    cudaGetSymbolAddress((void**)&bsum,   g_bsum);
    cudaGetSymbolAddress((void**)&rowptr, g_rowptr);
    cudaGetSymbolAddress((void**)&cursor, g_cursor);
    cudaGetSymbolAddress((void**)&col,    g_col);

    float* out = (float*)d_out;
    const int T = 256;
    const int NB = (N + 1023) / 1024;
    const int EQ = (E + 3) / 4;

    cudaStream_t s2;
    cudaEvent_t evFork, evCSR;
    cudaStreamCreateWithFlags(&s2, cudaStreamNonBlocking);
    cudaEventCreateWithFlags(&evFork, cudaEventDisableTiming);
    cudaEventCreateWithFlags(&evCSR,  cudaEventDisableTiming);

    cudaEventRecord(evFork, 0);
    cudaStreamWaitEvent(s2, evFork, 0);

    // --- CSR build on s2, concurrent with gemm1 on stream 0 ---
    cudaMemsetAsync(deg, 0, (size_t)N * sizeof(int), s2);
    deg_count_kernel<<<(EQ + T - 1) / T, T, 0, s2>>>(edst, deg, E);
    scan1_kernel    <<<NB, 1024, 0, s2>>>(deg, scn, bsum, N);
    fixup_kernel    <<<(N + T - 1) / T, T, 0, s2>>>(scn, deg, bsum,
                                                    rowptr, cursor, dis, N, E);
    fill_kernel     <<<(EQ + T - 1) / T, T, 0, s2>>>(esrc, edst, cursor, col, E);
    cudaEventRecord(evCSR, s2);

    // --- gemm1 (dis-free) on stream 0, concurrent with CSR build ---
    gemm_kernel<128, 64><<<(N + 127) / 128, 128>>>(x, W1, hs1, N);
    cudaStreamWaitEvent(0, evCSR, 0);

    // --- boundary 1: gather(l1) + gemm(l2), warp-local -> hs2 (pre-scaled) ---
    gather_gemm_kernel<64, true><<<(N * 16 + T - 1) / T, T>>>(
        rowptr, col, hs1, dis, b1, W2, hs2, N);

    // --- boundary 2: gather(l2) + gemm(l3), warp-local -> hs3 (pre-scaled) ---
    gather_gemm_kernel<32, false><<<(N * 16 + T - 1) / T, T>>>(
        rowptr, col, hs2, dis, b2, W3, hs3, N);

    // --- final gather (layer 3) -> out ---
    gather_f32_kernel<<<(N * 8 + T - 1) / T, T>>>(
        rowptr, col, hs3, dis, b3, out, N);

    cudaEventDestroy(evFork);
    cudaEventDestroy(evCSR);
    cudaStreamDestroy(s2);
}